// round 17
// baseline (speedup 1.0000x reference)
#include <cuda_runtime.h>
#include <cuda_bf16.h>
#include <cstdint>
#include <math.h>

#define B_ 4
#define T_ 2048
#define C_ 1024
#define H_ 16
#define D_ 64

// ---------------------------------------------------------------------------
// Scratch (allocation-free rule: __device__ globals)
// ---------------------------------------------------------------------------
__device__ __nv_bfloat16 g_qkvh[(size_t)B_ * T_ * 3 * C_];
__device__ __nv_bfloat16 g_qkvl[(size_t)B_ * T_ * 3 * C_];
__device__ __nv_bfloat16 g_xh[(size_t)B_ * T_ * C_];
__device__ __nv_bfloat16 g_xl[(size_t)B_ * T_ * C_];
__device__ __nv_bfloat16 g_yh[(size_t)B_ * T_ * C_];
__device__ __nv_bfloat16 g_yl[(size_t)B_ * T_ * C_];
__device__ __nv_bfloat16 g_wqh[(size_t)3 * C_ * C_];
__device__ __nv_bfloat16 g_wql[(size_t)3 * C_ * C_];
__device__ __nv_bfloat16 g_woh[(size_t)C_ * C_];
__device__ __nv_bfloat16 g_wol[(size_t)C_ * C_];

// ---------------------------------------------------------------------------
// Baseline-PTX helpers (all valid on compute_103: no tcgen05)
// ---------------------------------------------------------------------------
__device__ __forceinline__ uint32_t smem_u32(const void* p) {
    uint32_t a;
    asm("{ .reg .u64 t; cvta.to.shared.u64 t, %1; cvt.u32.u64 %0, t; }" : "=r"(a) : "l"(p));
    return a;
}
__device__ __forceinline__ uint32_t swz128(uint32_t off) { return off ^ ((off >> 3) & 0x70); }

__device__ __forceinline__ void cp_async16(uint32_t dst, const void* src) {
    asm volatile("cp.async.cg.shared.global [%0], [%1], 16;" :: "r"(dst), "l"(src) : "memory");
}
#define CP_COMMIT()  asm volatile("cp.async.commit_group;" ::: "memory")
#define CP_WAIT(n)   asm volatile("cp.async.wait_group %0;" :: "n"(n) : "memory")

#define LDSM_X4(r0, r1, r2, r3, addr) \
    asm volatile("ldmatrix.sync.aligned.m8n8.x4.shared.b16 {%0,%1,%2,%3}, [%4];" \
        : "=r"(r0), "=r"(r1), "=r"(r2), "=r"(r3) : "r"(addr))

#define LDSM_X4_T(r0, r1, r2, r3, addr) \
    asm volatile("ldmatrix.sync.aligned.m8n8.x4.trans.shared.b16 {%0,%1,%2,%3}, [%4];" \
        : "=r"(r0), "=r"(r1), "=r"(r2), "=r"(r3) : "r"(addr))

#define MMA16816(d, a, b) \
    asm volatile("mma.sync.aligned.m16n8k16.row.col.f32.bf16.bf16.f32 " \
        "{%0,%1,%2,%3}, {%4,%5,%6,%7}, {%8,%9}, {%0,%1,%2,%3};" \
        : "+f"((d)[0]), "+f"((d)[1]), "+f"((d)[2]), "+f"((d)[3]) \
        : "r"((a)[0]), "r"((a)[1]), "r"((a)[2]), "r"((a)[3]), "r"((b)[0]), "r"((b)[1]))

__device__ __forceinline__ uint32_t pack_bf16x2(float lo, float hi) {
    uint32_t r;
    asm("cvt.rn.bf16x2.f32 %0, %1, %2;" : "=r"(r) : "f"(hi), "f"(lo));
    return r;
}
__device__ __forceinline__ float bf16lo_f(uint32_t p) { return __uint_as_float(p << 16); }
__device__ __forceinline__ float bf16hi_f(uint32_t p) { return __uint_as_float(p & 0xffff0000u); }

// ---------------------------------------------------------------------------
// Fused hi/lo bf16 split of ALL THREE fp32 inputs in one launch
// ---------------------------------------------------------------------------
__global__ __launch_bounds__(256) void split3_kernel(
    const float* __restrict__ s0, __nv_bfloat16* __restrict__ h0, __nv_bfloat16* __restrict__ l0, int n0,
    const float* __restrict__ s1, __nv_bfloat16* __restrict__ h1, __nv_bfloat16* __restrict__ l1, int n1,
    const float* __restrict__ s2, __nv_bfloat16* __restrict__ h2, __nv_bfloat16* __restrict__ l2, int n2)
{
    int i = blockIdx.x * 256 + threadIdx.x;
    const float* s;
    __nv_bfloat16 *h, *l;
    int j;
    if (i < n0)              { s = s0; h = h0; l = l0; j = i; }
    else if (i < n0 + n1)    { s = s1; h = h1; l = l1; j = i - n0; }
    else if (i < n0 + n1 + n2) { s = s2; h = h2; l = l2; j = i - n0 - n1; }
    else return;

    float4 v = ((const float4*)s)[j];
    uint32_t h01 = pack_bf16x2(v.x, v.y), h23 = pack_bf16x2(v.z, v.w);
    uint32_t l01 = pack_bf16x2(v.x - bf16lo_f(h01), v.y - bf16hi_f(h01));
    uint32_t l23 = pack_bf16x2(v.z - bf16lo_f(h23), v.w - bf16hi_f(h23));
    uint32_t* hp = (uint32_t*)(h + 4 * (size_t)j);
    uint32_t* lp = (uint32_t*)(l + 4 * (size_t)j);
    hp[0] = h01; hp[1] = h23;
    lp[0] = l01; lp[1] = l23;
}

// ---------------------------------------------------------------------------
// mma.sync bf16x3 GEMM — FROZEN R13 config (343us, tensor 74%).
// CTA tile 128(M) x 64(N), warp tile 32x32, BK=64, 2-stage, 2 CTAs/SM.
// OUT[m,n] = sum_k A[m,k]*B[n,k];  D = Ah*Bh + Ah*Bl + Al*Bh
// ---------------------------------------------------------------------------
#define G_STAGE 49152
#define G_AH 0
#define G_AL 16384
#define G_BH 32768
#define G_BL 40960
#define G_TOTAL (2 * G_STAGE)

template <bool BF16OUT>
__global__ __launch_bounds__(256, 2) void gemm_bf16x3(
    const __nv_bfloat16* __restrict__ Ah, const __nv_bfloat16* __restrict__ Al,
    const __nv_bfloat16* __restrict__ Bh, const __nv_bfloat16* __restrict__ Bl,
    float* __restrict__ OUT,
    __nv_bfloat16* __restrict__ OUTH, __nv_bfloat16* __restrict__ OUTL,
    int N, int K)
{
    extern __shared__ char smem[];
    const uint32_t sb = smem_u32(smem);
    const int tid  = threadIdx.x;
    const int lane = tid & 31;
    const int warp = tid >> 5;
    const int wm   = warp >> 1;
    const int wn   = warp & 1;

    const size_t arow0 = (size_t)blockIdx.y * 128;
    const size_t brow0 = (size_t)blockIdx.x * 64;
    const __nv_bfloat16* pAh = Ah + arow0 * K;
    const __nv_bfloat16* pAl = Al + arow0 * K;
    const __nv_bfloat16* pBh = Bh + brow0 * K;
    const __nv_bfloat16* pBl = Bl + brow0 * K;

    const int nchunks = K >> 6;

    auto issue = [&](int ch) {
        const int k0 = ch << 6;
        const uint32_t s0 = sb + (ch & 1) * G_STAGE;
#pragma unroll
        for (int i = 0; i < 4; i++) {
            int ci = tid + i * 256;
            int r = ci >> 3, c = ci & 7;
            uint32_t so = swz128((uint32_t)(r * 128 + c * 16));
            size_t go = (size_t)r * K + k0 + c * 8;
            cp_async16(s0 + G_AH + so, pAh + go);
            cp_async16(s0 + G_AL + so, pAl + go);
        }
#pragma unroll
        for (int i = 0; i < 2; i++) {
            int ci = tid + i * 256;
            int r = ci >> 3, c = ci & 7;
            uint32_t so = swz128((uint32_t)(r * 128 + c * 16));
            size_t go = (size_t)r * K + k0 + c * 8;
            cp_async16(s0 + G_BH + so, pBh + go);
            cp_async16(s0 + G_BL + so, pBl + go);
        }
        CP_COMMIT();
    };

    float acc[2][4][4];
#pragma unroll
    for (int mt = 0; mt < 2; mt++)
#pragma unroll
        for (int nt = 0; nt < 4; nt++)
#pragma unroll
            for (int r = 0; r < 4; r++) acc[mt][nt][r] = 0.f;

    const int a_r  = lane & 15;
    const int a_k  = (lane >> 4) * 8;
    const int b_rr = lane & 7;
    const int b_g  = lane >> 3;
    const int b_n  = ((b_g >> 1) * 8) + b_rr;
    const int b_k  = (b_g & 1) * 8;

    issue(0);

    for (int ch = 0; ch < nchunks; ch++) {
        if (ch + 1 < nchunks) { issue(ch + 1); CP_WAIT(1); }
        else                  { CP_WAIT(0); }
        __syncthreads();

        const uint32_t s0 = sb + (ch & 1) * G_STAGE;
#pragma unroll
        for (int ks = 0; ks < 4; ks++) {
            const int kk = ks * 16;
            uint32_t fAh[2][4], fAl[2][4];
#pragma unroll
            for (int mt = 0; mt < 2; mt++) {
                uint32_t bo = swz128((uint32_t)((wm * 32 + mt * 16 + a_r) * 128 + (kk + a_k) * 2));
                LDSM_X4(fAh[mt][0], fAh[mt][1], fAh[mt][2], fAh[mt][3], s0 + G_AH + bo);
                LDSM_X4(fAl[mt][0], fAl[mt][1], fAl[mt][2], fAl[mt][3], s0 + G_AL + bo);
            }
            uint32_t fBh[4][2], fBl[4][2];
#pragma unroll
            for (int p = 0; p < 2; p++) {
                uint32_t bo = swz128((uint32_t)((wn * 32 + p * 16 + b_n) * 128 + (kk + b_k) * 2));
                uint32_t r0, r1, r2, r3;
                LDSM_X4(r0, r1, r2, r3, s0 + G_BH + bo);
                fBh[p*2][0] = r0; fBh[p*2][1] = r1; fBh[p*2+1][0] = r2; fBh[p*2+1][1] = r3;
                LDSM_X4(r0, r1, r2, r3, s0 + G_BL + bo);
                fBl[p*2][0] = r0; fBl[p*2][1] = r1; fBl[p*2+1][0] = r2; fBl[p*2+1][1] = r3;
            }
#pragma unroll
            for (int mt = 0; mt < 2; mt++)
#pragma unroll
                for (int nt = 0; nt < 4; nt++) MMA16816(acc[mt][nt], fAh[mt], fBh[nt]);
#pragma unroll
            for (int mt = 0; mt < 2; mt++)
#pragma unroll
                for (int nt = 0; nt < 4; nt++) MMA16816(acc[mt][nt], fAh[mt], fBl[nt]);
#pragma unroll
            for (int mt = 0; mt < 2; mt++)
#pragma unroll
                for (int nt = 0; nt < 4; nt++) MMA16816(acc[mt][nt], fAl[mt], fBh[nt]);
        }
        __syncthreads();
    }

    const int c_r = lane >> 2;
    const int c_c = (lane & 3) * 2;
#pragma unroll
    for (int mt = 0; mt < 2; mt++) {
        size_t row = arow0 + wm * 32 + mt * 16 + c_r;
        size_t off0 = row * N       + brow0 + wn * 32 + c_c;
        size_t off1 = (row + 8) * N + brow0 + wn * 32 + c_c;
        if (BF16OUT) {
#pragma unroll
            for (int nt = 0; nt < 4; nt++) {
                float y0 = acc[mt][nt][0], y1 = acc[mt][nt][1];
                float y2 = acc[mt][nt][2], y3 = acc[mt][nt][3];
                uint32_t h01 = pack_bf16x2(y0, y1);
                uint32_t l01 = pack_bf16x2(y0 - bf16lo_f(h01), y1 - bf16hi_f(h01));
                uint32_t h23 = pack_bf16x2(y2, y3);
                uint32_t l23 = pack_bf16x2(y2 - bf16lo_f(h23), y3 - bf16hi_f(h23));
                *(uint32_t*)(OUTH + off0 + nt * 8) = h01;
                *(uint32_t*)(OUTL + off0 + nt * 8) = l01;
                *(uint32_t*)(OUTH + off1 + nt * 8) = h23;
                *(uint32_t*)(OUTL + off1 + nt * 8) = l23;
            }
        } else {
#pragma unroll
            for (int nt = 0; nt < 4; nt++) {
                *(float2*)(OUT + off0 + nt * 8) = make_float2(acc[mt][nt][0], acc[mt][nt][1]);
                *(float2*)(OUT + off1 + nt * 8) = make_float2(acc[mt][nt][2], acc[mt][nt][3]);
            }
        }
    }
}

// ---------------------------------------------------------------------------
// Tensor-core causal flash attention (R16 config) + LPT scheduling:
// qt reversed so longest CTAs (most key blocks) launch first.
// KEY BLOCK = 128; 1 CTA/SM; 2-stage K/V pipeline (160KB smem).
// ---------------------------------------------------------------------------
#define AQ_H 0
#define AQ_L 16384
#define A_STG 32768          // stage base; per stage: KH 0, KL 16K, VH 32K, VL 48K
#define A_SSZ 65536
#define A_TOTAL (A_STG + 2 * A_SSZ)   // 160KB, 1 CTA/SM

__global__ __launch_bounds__(256, 1) void attn_mma(
    const __nv_bfloat16* __restrict__ qkvh, const __nv_bfloat16* __restrict__ qkvl,
    __nv_bfloat16* __restrict__ yh, __nv_bfloat16* __restrict__ yl)
{
    extern __shared__ char smem[];
    const uint32_t sb = smem_u32(smem);
    const int qt   = gridDim.x - 1 - blockIdx.x;   // LPT: longest first
    const int h    = blockIdx.y;
    const int b    = blockIdx.z;
    const int tid  = threadIdx.x;
    const int lane = tid & 31;
    const int warp = tid >> 5;

    const size_t rs = (size_t)3 * C_;
    const __nv_bfloat16* Qh = qkvh + ((size_t)(b * T_ + qt * 128)) * rs + h * D_;
    const __nv_bfloat16* Ql = qkvl + ((size_t)(b * T_ + qt * 128)) * rs + h * D_;
    const __nv_bfloat16* Kh = qkvh + ((size_t)b * T_) * rs + C_     + h * D_;
    const __nv_bfloat16* Kl = qkvl + ((size_t)b * T_) * rs + C_     + h * D_;
    const __nv_bfloat16* Vh = qkvh + ((size_t)b * T_) * rs + 2 * C_ + h * D_;
    const __nv_bfloat16* Vl = qkvl + ((size_t)b * T_) * rs + 2 * C_ + h * D_;

    // ---- Q tile loads (group 0) ----
#pragma unroll
    for (int i = 0; i < 4; i++) {
        int lin = i * 256 + tid;
        int r = lin >> 3, c = lin & 7;
        uint32_t so = swz128((uint32_t)(r * 128 + c * 16));
        cp_async16(sb + AQ_H + so, Qh + (size_t)r * rs + c * 8);
        cp_async16(sb + AQ_L + so, Ql + (size_t)r * rs + c * 8);
    }
    CP_COMMIT();

    // 128-key block loader: K/V hi+lo, 128 rows x 128B each tile
    auto issue_blk = [&](int kb) {
        const uint32_t s0 = sb + A_STG + (kb & 1) * A_SSZ;
        const size_t g0 = (size_t)(kb * 128) * rs;
#pragma unroll
        for (int i = 0; i < 4; i++) {
            int lin = i * 256 + tid;             // 0..1023
            int r = lin >> 3, c = lin & 7;
            uint32_t so = swz128((uint32_t)(r * 128 + c * 16));
            size_t go = g0 + (size_t)r * rs + c * 8;
            cp_async16(s0 + 0     + so, Kh + go);
            cp_async16(s0 + 16384 + so, Kl + go);
            cp_async16(s0 + 32768 + so, Vh + go);
            cp_async16(s0 + 49152 + so, Vl + go);
        }
        CP_COMMIT();
    };

    const int nb = qt + 1;             // 128-key blocks
    issue_blk(0);
    CP_WAIT(1);                        // Q done (blk0 may be in flight)
    __syncthreads();

    // ---- Q fragments (resident) ----
    const int a_r = lane & 15, a_k = (lane >> 4) * 8;
    uint32_t fQh[4][4], fQl[4][4];
#pragma unroll
    for (int ks = 0; ks < 4; ks++) {
        uint32_t bo = swz128((uint32_t)((warp * 16 + a_r) * 128 + (ks * 16 + a_k) * 2));
        LDSM_X4(fQh[ks][0], fQh[ks][1], fQh[ks][2], fQh[ks][3], sb + AQ_H + bo);
        LDSM_X4(fQl[ks][0], fQl[ks][1], fQl[ks][2], fQl[ks][3], sb + AQ_L + bo);
    }

    float oacc[8][4];
#pragma unroll
    for (int j = 0; j < 8; j++)
#pragma unroll
        for (int r = 0; r < 4; r++) oacc[j][r] = 0.f;
    float mrow[2] = {-1e30f, -1e30f};
    float lrow[2] = {0.f, 0.f};

    const int b_rr = lane & 7, b_g = lane >> 3;
    const int b_row = (b_g >> 1) * 8 + b_rr;
    const int b_k   = (b_g & 1) * 8;
    const int qg0 = qt * 128 + warp * 16 + (lane >> 2);

    for (int kb = 0; kb < nb; kb++) {
        if (kb + 1 < nb) { issue_blk(kb + 1); CP_WAIT(1); }
        else             { CP_WAIT(0); }
        __syncthreads();               // stage kb published

        const uint32_t sK = sb + A_STG + (kb & 1) * A_SSZ;
        const uint32_t sV = sK + 32768;

        // ---- S = Q K^T over 128 keys (bf16x3) ----
        float sacc[16][4];
#pragma unroll
        for (int j = 0; j < 16; j++)
#pragma unroll
            for (int r = 0; r < 4; r++) sacc[j][r] = 0.f;
#pragma unroll
        for (int ks = 0; ks < 4; ks++) {
#pragma unroll
            for (int p = 0; p < 8; p++) {
                uint32_t bo = swz128((uint32_t)((p * 16 + b_row) * 128 + (ks * 16 + b_k) * 2));
                uint32_t bh[2][2], bl[2][2], r0, r1, r2, r3;
                LDSM_X4(r0, r1, r2, r3, sK + bo);
                bh[0][0] = r0; bh[0][1] = r1; bh[1][0] = r2; bh[1][1] = r3;
                LDSM_X4(r0, r1, r2, r3, sK + 16384 + bo);
                bl[0][0] = r0; bl[0][1] = r1; bl[1][0] = r2; bl[1][1] = r3;
                MMA16816(sacc[2*p],   fQh[ks], bh[0]);
                MMA16816(sacc[2*p+1], fQh[ks], bh[1]);
                MMA16816(sacc[2*p],   fQh[ks], bl[0]);
                MMA16816(sacc[2*p+1], fQh[ks], bl[1]);
                MMA16816(sacc[2*p],   fQl[ks], bh[0]);
                MMA16816(sacc[2*p+1], fQl[ks], bh[1]);
            }
        }

        // ---- scale + causal mask (diagonal block only: kb == qt) ----
#pragma unroll
        for (int j = 0; j < 16; j++)
#pragma unroll
            for (int r = 0; r < 4; r++) sacc[j][r] *= 0.125f;
        if (kb == qt) {
            const int kbase = kb * 128 + (lane & 3) * 2;
#pragma unroll
            for (int j = 0; j < 16; j++) {
#pragma unroll
                for (int cc = 0; cc < 2; cc++) {
                    int kg = kbase + j * 8 + cc;
                    if (kg > qg0)     sacc[j][cc]     = -1e30f;
                    if (kg > qg0 + 8) sacc[j][2 + cc] = -1e30f;
                }
            }
        }

        // ---- online softmax (once per 128 keys) ----
        float m0 = mrow[0], m1 = mrow[1];
#pragma unroll
        for (int j = 0; j < 16; j++) {
            m0 = fmaxf(m0, fmaxf(sacc[j][0], sacc[j][1]));
            m1 = fmaxf(m1, fmaxf(sacc[j][2], sacc[j][3]));
        }
        m0 = fmaxf(m0, __shfl_xor_sync(0xffffffffu, m0, 1));
        m0 = fmaxf(m0, __shfl_xor_sync(0xffffffffu, m0, 2));
        m1 = fmaxf(m1, __shfl_xor_sync(0xffffffffu, m1, 1));
        m1 = fmaxf(m1, __shfl_xor_sync(0xffffffffu, m1, 2));
        const float f0 = __expf(mrow[0] - m0), f1 = __expf(mrow[1] - m1);
        mrow[0] = m0; mrow[1] = m1;
        lrow[0] *= f0; lrow[1] *= f1;
#pragma unroll
        for (int j = 0; j < 8; j++) {
            oacc[j][0] *= f0; oacc[j][1] *= f0;
            oacc[j][2] *= f1; oacc[j][3] *= f1;
        }

        // p = exp(s - m) packed into PV A-frags (8 k-steps of 16 keys)
        uint32_t ah[8][4], al[8][4];
#pragma unroll
        for (int j = 0; j < 16; j++) {
            float p0 = __expf(sacc[j][0] - m0);
            float p1 = __expf(sacc[j][1] - m0);
            float p2 = __expf(sacc[j][2] - m1);
            float p3 = __expf(sacc[j][3] - m1);
            lrow[0] += p0 + p1;
            lrow[1] += p2 + p3;
            uint32_t ph01 = pack_bf16x2(p0, p1);
            uint32_t ph23 = pack_bf16x2(p2, p3);
            uint32_t pl01 = pack_bf16x2(p0 - bf16lo_f(ph01), p1 - bf16hi_f(ph01));
            uint32_t pl23 = pack_bf16x2(p2 - bf16lo_f(ph23), p3 - bf16hi_f(ph23));
            const int ks = j >> 1, sl = (j & 1) * 2;
            ah[ks][sl]     = ph01;  ah[ks][sl + 1] = ph23;
            al[ks][sl]     = pl01;  al[ks][sl + 1] = pl23;
        }

        // ---- O += P V over 128 keys (V^T frags via ldmatrix.trans) ----
#pragma unroll
        for (int ks = 0; ks < 8; ks++) {
#pragma unroll
            for (int p = 0; p < 4; p++) {
                uint32_t bo = swz128((uint32_t)((ks * 16 + (b_g & 1) * 8 + b_rr) * 128 +
                                                (p * 16 + (b_g >> 1) * 8) * 2));
                uint32_t vh[2][2], vl[2][2], r0, r1, r2, r3;
                LDSM_X4_T(r0, r1, r2, r3, sV + bo);
                vh[0][0] = r0; vh[0][1] = r1; vh[1][0] = r2; vh[1][1] = r3;
                LDSM_X4_T(r0, r1, r2, r3, sV + 16384 + bo);
                vl[0][0] = r0; vl[0][1] = r1; vl[1][0] = r2; vl[1][1] = r3;
                MMA16816(oacc[2*p],   ah[ks], vh[0]);
                MMA16816(oacc[2*p+1], ah[ks], vh[1]);
                MMA16816(oacc[2*p],   ah[ks], vl[0]);
                MMA16816(oacc[2*p+1], ah[ks], vl[1]);
                MMA16816(oacc[2*p],   al[ks], vh[0]);
                MMA16816(oacc[2*p+1], al[ks], vh[1]);
            }
        }
        __syncthreads();               // before stage reuse (2-stage ring)
    }

    // ---- finalize ----
    lrow[0] += __shfl_xor_sync(0xffffffffu, lrow[0], 1);
    lrow[0] += __shfl_xor_sync(0xffffffffu, lrow[0], 2);
    lrow[1] += __shfl_xor_sync(0xffffffffu, lrow[1], 1);
    lrow[1] += __shfl_xor_sync(0xffffffffu, lrow[1], 2);
    const float inv0 = 1.f / lrow[0], inv1 = 1.f / lrow[1];

    const int t0 = qt * 128 + warp * 16 + (lane >> 2);
    const size_t base0 = ((size_t)(b * T_ + t0)) * C_ + h * D_ + (lane & 3) * 2;
    const size_t base1 = base0 + 8 * (size_t)C_;
#pragma unroll
    for (int j = 0; j < 8; j++) {
        float y0 = oacc[j][0] * inv0, y1 = oacc[j][1] * inv0;
        float y2 = oacc[j][2] * inv1, y3 = oacc[j][3] * inv1;
        uint32_t h01 = pack_bf16x2(y0, y1);
        uint32_t l01 = pack_bf16x2(y0 - bf16lo_f(h01), y1 - bf16hi_f(h01));
        uint32_t h23 = pack_bf16x2(y2, y3);
        uint32_t l23 = pack_bf16x2(y2 - bf16lo_f(h23), y3 - bf16hi_f(h23));
        *(uint32_t*)(yh + base0 + j * 8) = h01;
        *(uint32_t*)(yl + base0 + j * 8) = l01;
        *(uint32_t*)(yh + base1 + j * 8) = h23;
        *(uint32_t*)(yl + base1 + j * 8) = l23;
    }
}

// ---------------------------------------------------------------------------
extern "C" void kernel_launch(void* const* d_in, const int* in_sizes, int n_in,
                              void* d_out, int out_size)
{
    const float* x     = (const float*)d_in[0];   // [B,T,C]
    const float* w_qkv = (const float*)d_in[1];   // [3C,C]
    const float* w_out = (const float*)d_in[2];   // [C,C]
    float* out = (float*)d_out;                   // [B,T,C]

    __nv_bfloat16 *qkvh, *qkvl, *xh, *xl, *yh, *yl, *wqh, *wql, *woh, *wol;
    cudaGetSymbolAddress((void**)&qkvh, g_qkvh); cudaGetSymbolAddress((void**)&qkvl, g_qkvl);
    cudaGetSymbolAddress((void**)&xh,  g_xh);  cudaGetSymbolAddress((void**)&xl,  g_xl);
    cudaGetSymbolAddress((void**)&yh,  g_yh);  cudaGetSymbolAddress((void**)&yl,  g_yl);
    cudaGetSymbolAddress((void**)&wqh, g_wqh); cudaGetSymbolAddress((void**)&wql, g_wql);
    cudaGetSymbolAddress((void**)&woh, g_woh); cudaGetSymbolAddress((void**)&wol, g_wol);

    cudaFuncSetAttribute(gemm_bf16x3<true>,  cudaFuncAttributeMaxDynamicSharedMemorySize, G_TOTAL);
    cudaFuncSetAttribute(gemm_bf16x3<false>, cudaFuncAttributeMaxDynamicSharedMemorySize, G_TOTAL);
    cudaFuncSetAttribute(attn_mma,           cudaFuncAttributeMaxDynamicSharedMemorySize, A_TOTAL);

    const int M = B_ * T_;                  // 8192
    const int n_x  = M * C_ / 4;            // float4 counts
    const int n_wq = 3 * C_ * C_ / 4;
    const int n_wo = C_ * C_ / 4;

    // fused hi/lo splits (single launch)
    {
        int total = n_x + n_wq + n_wo;
        split3_kernel<<<(total + 255) / 256, 256>>>(
            x, xh, xl, n_x,
            w_qkv, wqh, wql, n_wq,
            w_out, woh, wol, n_wo);
    }

    // 1) qkv = x @ w_qkv^T -> bf16 hi/lo directly
    {
        dim3 grid(3 * C_ / 64, M / 128);
        gemm_bf16x3<true><<<grid, 256, G_TOTAL>>>(xh, xl, wqh, wql,
                                                  nullptr, qkvh, qkvl, 3 * C_, C_);
    }
    // 2) causal attention (bf16 in, bf16 hi/lo out), 128-key blocks, LPT order
    {
        dim3 grid(T_ / 128, H_, B_);
        attn_mma<<<grid, 256, A_TOTAL>>>(qkvh, qkvl, yh, yl);
    }
    // 3) out = y @ w_out^T -> fp32
    {
        dim3 grid(C_ / 64, M / 128);
        gemm_bf16x3<false><<<grid, 256, G_TOTAL>>>(yh, yl, woh, wol,
                                                   out, nullptr, nullptr, C_, C_);
    }
}